// round 5
// baseline (speedup 1.0000x reference)
#include <cuda_runtime.h>
#include <cstdint>

// Problem constants (fixed shapes for this problem)
#define IMG_H 1536
#define IMG_W 1536
#define NB    4
#define TO    28          // output tile edge
#define NT    55          // ceil(1536/28)

typedef unsigned long long ull;

// ---------------- f32x2 packed helpers (sm_103a) ----------------
__device__ __forceinline__ ull pk2(float lo, float hi) {
    ull r;
    asm("mov.b64 %0, {%1, %2};" : "=l"(r) : "f"(lo), "f"(hi));
    return r;
}
__device__ __forceinline__ void ffma2(ull& d, ull a, ull b) {
    asm("fma.rn.f32x2 %0, %1, %2, %0;" : "+l"(d) : "l"(a), "l"(b));
}
__device__ __forceinline__ void unpk2(ull v, float& lo, float& hi) {
    asm("mov.b64 {%0, %1}, %2;" : "=f"(lo), "=f"(hi) : "l"(v));
}

// ---------------- fused conv block: 3x3, CIN in-channels, 16 out-channels,
// 2 output rows (r0, r1) x 2 output cols (col, col+1) per thread -------------
template<int CIN, int ISTR, int IPLANE>
__device__ __forceinline__ void conv_block(const float* __restrict__ sin,
                                           const float* __restrict__ swp,
                                           int col, int r0, int r1,
                                           ull acc[2][16]) {
#pragma unroll 1
    for (int cin = 0; cin < CIN; ++cin) {
        const float* base = sin + cin * IPLANE + col;
        ull pr[2][3][3];
#pragma unroll
        for (int k = 0; k < 2; ++k) {
            int r = k ? r1 : r0;
#pragma unroll
            for (int dy = 0; dy < 3; ++dy) {
                const float* p = base + (r + dy) * ISTR;
                float2 a = *(const float2*)p;         // cols col, col+1
                float2 b = *(const float2*)(p + 2);   // cols col+2, col+3
                pr[k][dy][0] = pk2(a.x, a.y);
                pr[k][dy][1] = pk2(a.y, b.x);
                pr[k][dy][2] = pk2(b.x, b.y);
            }
        }
        const ull* w = (const ull*)swp + cin * 9 * 16;
#pragma unroll
        for (int t = 0; t < 9; ++t) {
#pragma unroll
            for (int co = 0; co < 16; ++co) {
                ull wv = w[t * 16 + co];
                ffma2(acc[0][co], pr[0][t / 3][t % 3], wv);
                ffma2(acc[1][co], pr[1][t / 3][t % 3], wv);
            }
        }
    }
}

// smem layout (floats):
//  s_h1 : 16*32*34 = 17408   conv1 out (halo 2), row stride 34
//  s_h2 : 16*30*32 = 15360   conv2 out (halo 1), row stride 32
//  s_in : 3*34*36  = 3672    input tile (halo 3), row stride 36
//  s_w1 : 27*16*2  = 864     packed dup weights (w,w)
//  s_w2 : 144*16*2 = 4608
//  s_w3 : 144*16*2 = 4608
// total = 46520 floats = 186080 bytes
#define SMEM_BYTES 186080

__global__ __launch_bounds__(256, 1)
void net_fused_kernel(const float* __restrict__ x,
                      const float* __restrict__ w1,
                      const float* __restrict__ w2,
                      const float* __restrict__ w3,
                      float* __restrict__ out) {
    extern __shared__ float sm[];
    float* s_h1 = sm;
    float* s_h2 = s_h1 + 17408;
    float* s_in = s_h2 + 15360;
    float* s_w1 = s_in + 3672;
    float* s_w2 = s_w1 + 864;
    float* s_w3 = s_w2 + 4608;

    const int tid = threadIdx.x;
    const int tx = tid & 15;       // 0..15 -> column pair 2*tx
    const int ty = tid >> 4;       // 0..15 -> rows ty, ty+16
    const int ox = blockIdx.x * TO;
    const int oy = blockIdx.y * TO;
    const int bz = blockIdx.z;

    // ---- Stage A: load input halo tile (34x34x3, zero-padded) + weights ----
    {
        const float* xb = x + (size_t)bz * 3 * IMG_H * IMG_W;
        for (int i = tid; i < 3 * 34 * 34; i += 256) {
            int cin = i / 1156;
            int rem = i - cin * 1156;
            int rr  = rem / 34;
            int cc  = rem - rr * 34;
            int gy = oy - 3 + rr;
            int gx = ox - 3 + cc;
            float v = 0.0f;
            if ((unsigned)gy < IMG_H && (unsigned)gx < IMG_W)
                v = xb[(size_t)cin * IMG_H * IMG_W + (size_t)gy * IMG_W + gx];
            s_in[cin * 1224 + rr * 36 + cc] = v;
        }
        // w1: [16][3][3][3] -> s_w1[(cin*9+k)*16+co] duplicated
        for (int i = tid; i < 432; i += 256) {
            int co = i / 27;
            int rem = i - co * 27;            // cin*9 + ky*3 + kx
            float v = w1[i];
            ((float2*)s_w1)[rem * 16 + co] = make_float2(v, v);
        }
        // w2/w3: [16][16][3][3] -> [(cin*9+k)*16+co] duplicated
        for (int i = tid; i < 2304; i += 256) {
            int co = i / 144;
            int rem = i - co * 144;           // cin*9 + k
            float v2 = w2[i];
            float v3 = w3[i];
            ((float2*)s_w2)[rem * 16 + co] = make_float2(v2, v2);
            ((float2*)s_w3)[rem * 16 + co] = make_float2(v3, v3);
        }
    }
    __syncthreads();

    // ---- Stage B: conv1 (3 -> 16) over 32x32 region into s_h1 ----
    // IMPORTANT: intermediate values at positions OUTSIDE the image must be
    // exactly zero (the reference zero-pads every conv layer). Mask on store.
    {
        ull acc[2][16];
#pragma unroll
        for (int k = 0; k < 2; ++k)
#pragma unroll
            for (int c = 0; c < 16; ++c) acc[k][c] = 0ULL;

        conv_block<3, 36, 1224>(s_in, s_w1, 2 * tx, ty, ty + 16, acc);

        int gx = ox - 2 + 2 * tx;  // global col of lo component (halo-2)
#pragma unroll
        for (int k = 0; k < 2; ++k) {
            int r = k ? (ty + 16) : ty;
            int gy = oy - 2 + r;
            float rowm = ((unsigned)gy < IMG_H) ? 1.0f : 0.0f;
            float mlo = ((unsigned)gx < IMG_W) ? rowm : 0.0f;
            float mhi = ((unsigned)(gx + 1) < IMG_W) ? rowm : 0.0f;
            ull mask = pk2(mlo, mhi);
#pragma unroll
            for (int co = 0; co < 16; ++co) {
                ull v = acc[k][co];
                // v *= mask (packed)
                asm("mul.rn.f32x2 %0, %0, %1;" : "+l"(v) : "l"(mask));
                *(ull*)(s_h1 + co * 1088 + r * 34 + 2 * tx) = v;
            }
        }
    }
    __syncthreads();

    // ---- Stage C: conv2 (16 -> 16) over 30x30 region into s_h2 ----
    {
        ull acc[2][16];
#pragma unroll
        for (int k = 0; k < 2; ++k)
#pragma unroll
            for (int c = 0; c < 16; ++c) acc[k][c] = 0ULL;

        int r1 = (ty < 14) ? (ty + 16) : 0;   // clamp loads for inactive row
        conv_block<16, 34, 1088>(s_h1, s_w2, 2 * tx, ty, r1, acc);

        if (tx < 15) {
            int gx = ox - 1 + 2 * tx;  // global col of lo component (halo-1)
#pragma unroll
            for (int k = 0; k < 2; ++k) {
                if (k && ty >= 14) break;
                int r = k ? (ty + 16) : ty;
                int gy = oy - 1 + r;
                float rowm = ((unsigned)gy < IMG_H) ? 1.0f : 0.0f;
                float mlo = ((unsigned)gx < IMG_W) ? rowm : 0.0f;
                float mhi = ((unsigned)(gx + 1) < IMG_W) ? rowm : 0.0f;
                ull mask = pk2(mlo, mhi);
#pragma unroll
                for (int co = 0; co < 16; ++co) {
                    ull v = acc[k][co];
                    asm("mul.rn.f32x2 %0, %0, %1;" : "+l"(v) : "l"(mask));
                    *(ull*)(s_h2 + co * 960 + r * 32 + 2 * tx) = v;
                }
            }
        }
    }
    __syncthreads();

    // ---- Stage D: conv3 (16 -> 16) + ReLU over 28x28, store to global ----
    {
        ull acc[2][16];
#pragma unroll
        for (int k = 0; k < 2; ++k)
#pragma unroll
            for (int c = 0; c < 16; ++c) acc[k][c] = 0ULL;

        int r1 = (ty < 12) ? (ty + 16) : 0;
        conv_block<16, 32, 960>(s_h2, s_w3, 2 * tx, ty, r1, acc);

        if (tx < 14) {
#pragma unroll
            for (int k = 0; k < 2; ++k) {
                if (k && ty >= 12) break;
                int r = k ? (ty + 16) : ty;
                int gy = oy + r;
                if (gy >= IMG_H) continue;
                int gx = ox + 2 * tx;
#pragma unroll
                for (int co = 0; co < 16; ++co) {
                    float lo, hi;
                    unpk2(acc[k][co], lo, hi);
                    lo = fmaxf(lo, 0.0f);
                    hi = fmaxf(hi, 0.0f);
                    float* po = out + ((size_t)(bz * 16 + co) * IMG_H + gy) * IMG_W + gx;
                    if (gx + 1 < IMG_W)      *(float2*)po = make_float2(lo, hi);
                    else if (gx < IMG_W)     *po = lo;
                }
            }
        }
    }
}

extern "C" void kernel_launch(void* const* d_in, const int* in_sizes, int n_in,
                              void* d_out, int out_size) {
    const float* x  = (const float*)d_in[0];
    const float* w1 = (const float*)d_in[1];
    const float* w2 = (const float*)d_in[2];
    const float* w3 = (const float*)d_in[3];
    float* out = (float*)d_out;

    cudaFuncSetAttribute(net_fused_kernel,
                         cudaFuncAttributeMaxDynamicSharedMemorySize, SMEM_BYTES);

    dim3 grid(NT, NT, NB);
    net_fused_kernel<<<grid, 256, SMEM_BYTES>>>(x, w1, w2, w3, out);
}